// round 9
// baseline (speedup 1.0000x reference)
#include <cuda_runtime.h>
#include <cuda_bf16.h>
#include <cstdint>

// Problem constants
#define Bn    8
#define Tt    16
#define Dd    768
#define NHh   12
#define HDm   64
#define HIDd  3072
#define HW    196
#define Npos  3136
#define SEQT  1568
#define NTOK_T 25088
#define BT    128
#define SSP   197
#define NTOK_S 25216
#define NROWS 25096

// tcgen05 is arch-accelerated: legal only in the sm_103a-specific pass.
#if defined(__CUDA_ARCH_FEAT_SM103_ALL)
#define TC_OK 1
#elif defined(__CUDA_ARCH_SPECIFIC__) && (__CUDA_ARCH_SPECIFIC__ == 1030)
#define TC_OK 1
#else
#define TC_OK 0
#endif

// ---------------- scratch (device globals; no runtime alloc) ----------------
__device__ __align__(16) float g_qkv[(size_t)NTOK_S * 3 * Dd];
__device__ __align__(16) __nv_bfloat16 g_hidh[(size_t)NROWS * HIDd];
__device__ __align__(16) __nv_bfloat16 g_hidl[(size_t)NROWS * HIDd];
__device__ __align__(16) __nv_bfloat16 g_lnh[(size_t)NTOK_S * Dd];
__device__ __align__(16) __nv_bfloat16 g_lnl[(size_t)NTOK_S * Dd];
__device__ __align__(16) __nv_bfloat16 g_atth[(size_t)NTOK_S * Dd];
__device__ __align__(16) __nv_bfloat16 g_attl[(size_t)NTOK_S * Dd];
__device__ __align__(16) __nv_bfloat16 g_tmph[(size_t)NTOK_T * Dd];
__device__ __align__(16) __nv_bfloat16 g_tmpl[(size_t)NTOK_T * Dd];
__device__ __align__(16) float g_xt2[(size_t)NTOK_T * Dd];
__device__ __align__(16) float g_rs [(size_t)NTOK_S * Dd];
#define WTOT 10027008
__device__ __align__(16) __nv_bfloat16 g_wh[WTOT];
__device__ __align__(16) __nv_bfloat16 g_wl[WTOT];
#define OFF_TQKV  0
#define OFF_TPROJ 1769472
#define OFF_TFC   2359296
#define OFF_SQKV  2949120
#define OFF_SPROJ 4718592
#define OFF_FC1   5308416
#define OFF_FC2   7667712

// ---------------- helpers -----------------------------------------------------
__device__ __forceinline__ float gelu_f(float v) {
    return 0.5f * v * (1.0f + erff(v * 0.70710678118654752f));
}
__device__ __forceinline__ void split_bf(float v, __nv_bfloat16& h, __nv_bfloat16& l) {
    h = __float2bfloat16(v);
    l = __float2bfloat16(v - __bfloat162float(h));
}
__device__ __forceinline__ uint32_t smem_u32(const void* p) {
    uint32_t a;
    asm("{ .reg .u64 t; cvta.to.shared.u64 t, %1; cvt.u32.u64 %0, t; }" : "=r"(a) : "l"(p));
    return a;
}
__device__ __forceinline__ uint32_t elect_one() {
    uint32_t p;
    asm volatile("{\n\t.reg .pred p;\n\telect.sync _|p, 0xFFFFFFFF;\n\tselp.b32 %0, 1, 0, p;\n\t}" : "=r"(p));
    return p;
}
__device__ __forceinline__ uint32_t ctarank() {
    uint32_t r;
    asm("mov.u32 %0, %%cluster_ctarank;" : "=r"(r));
    return r;
}

#define SWZ(b) ((b) ^ (((b) >> 3) & 0x70))

static constexpr uint64_t DESC_SW128 =
    (2ull << 61) | (1ull << 46) | (64ull << 32) | (1ull << 16);
__device__ __forceinline__ uint64_t mkdesc(uint32_t addr) {
    return DESC_SW128 | ((uint64_t)(addr >> 4) & 0x3FFF);
}

#define CLUSTER_SYNC() do { \
    asm volatile("barrier.cluster.arrive.aligned;" ::: "memory"); \
    asm volatile("barrier.cluster.wait.aligned;" ::: "memory"); } while (0)

#define MBAR_INIT(a, c) \
    asm volatile("mbarrier.init.shared.b64 [%0], %1;" :: "r"((uint32_t)(a)), "r"((uint32_t)(c)) : "memory")

// arrive on the SAME smem offset in cluster CTA 0 (leader)
#define MBAR_ARRIVE_RANK0(a) do { uint32_t _ra; \
    asm volatile("mapa.shared::cluster.u32 %0, %1, %2;" : "=r"(_ra) : "r"((uint32_t)(a)), "r"(0)); \
    asm volatile("mbarrier.arrive.shared::cluster.b64 _, [%0];" :: "r"(_ra) : "memory"); } while (0)

#define MBAR_WAIT(a, ph) do { \
    uint32_t _m = (uint32_t)(a), _p = (uint32_t)(ph), _d; \
    asm volatile("{\n\t.reg .pred p;\n\t" \
        "mbarrier.try_wait.parity.acquire.cta.shared::cta.b64 p, [%1], %2;\n\t" \
        "selp.b32 %0, 1, 0, p;\n\t}" : "=r"(_d) : "r"(_m), "r"(_p) : "memory"); \
    if (!_d) { \
        asm volatile("{\n\t.reg .pred P1;\n\t" \
            "WL_%=:\n\t" \
            "mbarrier.try_wait.parity.acquire.cta.shared::cta.b64 P1, [%0], %1, 0x989680;\n\t" \
            "@P1 bra.uni WD_%=;\n\t" \
            "bra.uni WL_%=;\n\t" \
            "WD_%=:\n\t}" :: "r"(_m), "r"(_p) : "memory"); \
    } \
} while (0)

// cluster-scope acquire variant (leader waiting for peer fill)
#define MBAR_WAIT_CLU(a, ph) do { \
    uint32_t _m = (uint32_t)(a), _p = (uint32_t)(ph), _d; \
    asm volatile("{\n\t.reg .pred p;\n\t" \
        "mbarrier.try_wait.parity.acquire.cluster.shared::cta.b64 p, [%1], %2;\n\t" \
        "selp.b32 %0, 1, 0, p;\n\t}" : "=r"(_d) : "r"(_m), "r"(_p) : "memory"); \
    if (!_d) { \
        asm volatile("{\n\t.reg .pred P1;\n\t" \
            "WL_%=:\n\t" \
            "mbarrier.try_wait.parity.acquire.cluster.shared::cta.b64 P1, [%0], %1, 0x989680;\n\t" \
            "@P1 bra.uni WD_%=;\n\t" \
            "bra.uni WL_%=;\n\t" \
            "WD_%=:\n\t}" :: "r"(_m), "r"(_p) : "memory"); \
    } \
} while (0)

#if TC_OK
#define TC_ALLOC_CG2(smem_addr, n) \
    asm volatile("tcgen05.alloc.cta_group::2.sync.aligned.shared::cta.b32 [%0], %1;" \
        :: "r"((uint32_t)(smem_addr)), "r"((uint32_t)(n)) : "memory")
#define TC_DEALLOC_CG2(tm, n) \
    asm volatile("tcgen05.dealloc.cta_group::2.sync.aligned.b32 %0, %1;" :: "r"(tm), "r"((uint32_t)(n)))
#define TC_RELINQ_CG2() \
    asm volatile("tcgen05.relinquish_alloc_permit.cta_group::2.sync.aligned;")
#define TC_FENCE_AFTER()  asm volatile("tcgen05.fence::after_thread_sync;" ::: "memory")
#define TC_WAIT_LD()      asm volatile("tcgen05.wait::ld.sync.aligned;" ::: "memory")
#define TC_COMMIT_MC2(mbar) \
    asm volatile("tcgen05.commit.cta_group::2.mbarrier::arrive::one.shared::cluster.multicast::cluster.b64 [%0], %1;" \
        :: "r"((uint32_t)(mbar)), "h"((uint16_t)3) : "memory")

#define TC_LD_X32(r, tm) \
    asm volatile("tcgen05.ld.sync.aligned.32x32b.x32.b32 " \
        "{%0, %1, %2, %3, %4, %5, %6, %7, %8, %9, %10, %11, %12, %13, %14, %15, " \
        " %16, %17, %18, %19, %20, %21, %22, %23, %24, %25, %26, %27, %28, %29, %30, %31}, [%32];" \
        : "=r"((r)[0]),  "=r"((r)[1]),  "=r"((r)[2]),  "=r"((r)[3]), \
          "=r"((r)[4]),  "=r"((r)[5]),  "=r"((r)[6]),  "=r"((r)[7]), \
          "=r"((r)[8]),  "=r"((r)[9]),  "=r"((r)[10]), "=r"((r)[11]), \
          "=r"((r)[12]), "=r"((r)[13]), "=r"((r)[14]), "=r"((r)[15]), \
          "=r"((r)[16]), "=r"((r)[17]), "=r"((r)[18]), "=r"((r)[19]), \
          "=r"((r)[20]), "=r"((r)[21]), "=r"((r)[22]), "=r"((r)[23]), \
          "=r"((r)[24]), "=r"((r)[25]), "=r"((r)[26]), "=r"((r)[27]), \
          "=r"((r)[28]), "=r"((r)[29]), "=r"((r)[30]), "=r"((r)[31]) \
        : "r"(tm))

__device__ __forceinline__ void mma_f16_ss_cg2(uint32_t d, uint64_t a, uint64_t b,
                                               uint32_t idesc, uint32_t en) {
    asm volatile("{\n\t.reg .pred p;\n\tsetp.ne.u32 p, %5, 0;\n\t"
        "tcgen05.mma.cta_group::2.kind::f16 [%0], %1, %2, %3, "
        "{%4, %4, %4, %4, %4, %4, %4, %4}, p;\n\t}"
        :: "r"(d), "l"(a), "l"(b), "r"(idesc), "r"(0u), "r"(en) : "memory");
}
#endif  // TC_OK

// ---------------- weight transpose + split: W[K,N] f32 -> Wh/Wl [N,K] bf16 -----
__global__ __launch_bounds__(256) void wsplit(
    const float* __restrict__ W, int K, int N,
    __nv_bfloat16* __restrict__ Wh, __nv_bfloat16* __restrict__ Wl)
{
    __shared__ float t[32][33];
    const int n0 = blockIdx.x * 32, k0 = blockIdx.y * 32;
    const int lx = threadIdx.x & 31, ly = threadIdx.x >> 5;
    #pragma unroll
    for (int i = ly; i < 32; i += 8)
        t[i][lx] = W[(size_t)(k0 + i) * N + n0 + lx];
    __syncthreads();
    #pragma unroll
    for (int i = ly; i < 32; i += 8) {
        float v = t[lx][i];
        size_t o = (size_t)(n0 + i) * K + k0 + lx;
        __nv_bfloat16 h, l; split_bf(v, h, l);
        Wh[o] = h; Wl[o] = l;
    }
}

// ---------------- GEMM: C[M,N] = (Ah+Al)[M,K] @ (Bh+Bl)^T[K,N] -----------------
// cg2 2-CTA cooperative MMA: 256x256 tile per pair (128 M-rows + 128 B N-rows
// per CTA), BK=64, double-buffered, 3-pass bf16 error compensation.
// blockIdx.x = tileM*2 + rank (cluster (2,1,1)); blockIdx.y = tileN.
template<int GELU_, int RESMAP_, int ACCUM_, int OUTHL_>
__global__ __launch_bounds__(256, 1) __cluster_dims__(2, 1, 1)
void mma_gemm(
    int M, int N, int K,
    const __nv_bfloat16* __restrict__ Ah, const __nv_bfloat16* __restrict__ Al,
    const __nv_bfloat16* __restrict__ Bh, const __nv_bfloat16* __restrict__ Bl,
    const float* __restrict__ bias, const float* __restrict__ res,
    float* __restrict__ Cf,
    __nv_bfloat16* __restrict__ Ch, __nv_bfloat16* __restrict__ Cl)
{
#if TC_OK
    extern __shared__ char dsm[];
    const uint32_t raw = smem_u32(dsm);
    const uint32_t pad = (1024u - (raw & 1023u)) & 1023u;
    char* smp = dsm + pad;
    const uint32_t sb32 = raw + pad;

    const int tid = threadIdx.x;
    const int wid = tid >> 5, lane = tid & 31;
    const uint32_t rank = ctarank();
    const int tileM = blockIdx.x >> 1;
    const int rowBase = tileM * 256 + (int)rank * 128;   // this CTA's 128 A rows
    const int colBase = blockIdx.y * 256;                // pair's 256 N cols
    const int bRow0   = colBase + (int)rank * 128;       // this CTA's 128 B rows

    // header: [0] tmem ptr; ready0 @16, ready1 @24 (used on rank0); done0 @32, done1 @40
    if (wid == 0) {
        TC_ALLOC_CG2(sb32, 256);
        TC_RELINQ_CG2();
    }
    if (tid == 0) {
        MBAR_INIT(sb32 + 16, 2);
        MBAR_INIT(sb32 + 24, 2);
        MBAR_INIT(sb32 + 32, 1);
        MBAR_INIT(sb32 + 40, 1);
    }
    __syncthreads();
    uint32_t tmem_base;
    asm volatile("ld.shared.b32 %0, [%1];" : "=r"(tmem_base) : "r"(sb32));
    // both CTAs' mbarriers + TMEM alloc must be done before any cluster arrive
    CLUSTER_SYNC();

    // stage layout: 1024 + buf*65536 ; Ah +0, Al +16384, Bh +32768, Bl +49152
    auto fill = [&](int buf, int k0) {
        char* sb = smp + 1024 + buf * 65536;
        const size_t kb = (size_t)k0 * 2;
        #pragma unroll
        for (int it = 0; it < 4; it++) {
            int idx = it * 256 + tid;
            int r = idx >> 3, cc = (idx & 7) * 16;
            uint32_t so = SWZ(r * 128 + cc);
            // A: this CTA's 128 rows (hi+lo)
            uint4 vh = make_uint4(0, 0, 0, 0), vl = make_uint4(0, 0, 0, 0);
            int grow = rowBase + r;
            if (grow < M) {
                size_t go = (size_t)grow * K * 2 + kb + cc;
                vh = *(const uint4*)((const char*)Ah + go);
                vl = *(const uint4*)((const char*)Al + go);
            }
            *(uint4*)(sb + so)         = vh;
            *(uint4*)(sb + 16384 + so) = vl;
            // B: this CTA's 128 N-rows (hi+lo); N dims are multiples of 256
            size_t gb = (size_t)(bRow0 + r) * K * 2 + kb + cc;
            *(uint4*)(sb + 32768 + so) = *(const uint4*)((const char*)Bh + gb);
            *(uint4*)(sb + 49152 + so) = *(const uint4*)((const char*)Bl + gb);
        }
    };

    const uint32_t idesc = (1u << 4) | (1u << 7) | (1u << 10)
                         | ((256u / 8) << 17) | ((256u / 16) << 24);
    const int nStages = K / 64;

    fill(0, 0);
    __syncthreads();
    if (tid == 0) {
        asm volatile("fence.proxy.async;" ::: "memory");
        MBAR_ARRIVE_RANK0(sb32 + 16);      // ready[0]
    }

    int rph[2] = {0, 0};     // leader's ready phases
    int dph[2] = {0, 0};     // done phases (per CTA)
    for (int s = 0; s < nStages; s++) {
        const int cur = s & 1, nxt = cur ^ 1;
        // leader issues the pair MMA for stage s
        if (rank == 0 && wid == 0) {
            if (elect_one()) {
                MBAR_WAIT_CLU(sb32 + 16 + cur * 8, rph[cur]);
                rph[cur] ^= 1;
                const uint32_t tb32 = sb32 + 1024 + cur * 65536;
                const uint64_t dAh = mkdesc(tb32);
                const uint64_t dAl = mkdesc(tb32 + 16384);
                const uint64_t dBh = mkdesc(tb32 + 32768);
                const uint64_t dBl = mkdesc(tb32 + 49152);
                #pragma unroll
                for (int p = 0; p < 3; p++) {
                    const uint64_t da = (p == 1) ? dAl : dAh;
                    const uint64_t db = (p == 2) ? dBl : dBh;
                    #pragma unroll
                    for (int k16 = 0; k16 < 4; k16++)
                        mma_f16_ss_cg2(tmem_base, da + 2 * k16, db + 2 * k16, idesc,
                                       (s > 0) || (p > 0) || (k16 > 0));
                }
                TC_COMMIT_MC2(sb32 + 32 + cur * 8);   // done[cur] in BOTH CTAs
            }
        }
        // overlap: fill next buffer while stage s MMA runs
        if (s + 1 < nStages) {
            if (s >= 1) {   // buffer nxt last consumed at stage s-1
                MBAR_WAIT(sb32 + 32 + nxt * 8, dph[nxt]);
                dph[nxt] ^= 1;
            }
            fill(nxt, (s + 1) * 64);
            __syncthreads();
            if (tid == 0) {
                asm volatile("fence.proxy.async;" ::: "memory");
                MBAR_ARRIVE_RANK0(sb32 + 16 + nxt * 8);
            }
        }
    }
    // wait for the last stage's MMA
    MBAR_WAIT(sb32 + 32 + ((nStages - 1) & 1) * 8, dph[(nStages - 1) & 1]);
    TC_FENCE_AFTER();

    // ---- epilogue: this CTA's 128 rows x 256 cols live in its own TMEM
    const int w4 = wid & 3;
    const int whalf = (wid >> 2) * 128;
    const int row = rowBase + w4 * 32 + lane;
    const bool valid = row < M;
    for (int c0 = 0; c0 < 128; c0 += 32) {
        uint32_t r32[32];
        TC_LD_X32(r32, tmem_base + whalf + c0);
        TC_WAIT_LD();
        if (valid) {
            const int col = colBase + whalf + c0;
            float v[32];
            #pragma unroll
            for (int j = 0; j < 32; j++) {
                v[j] = __uint_as_float(r32[j]);
                if (bias) v[j] += bias[col + j];
                if (GELU_) v[j] = gelu_f(v[j]);
            }
            if (RESMAP_ == 2) {
                const int bb = row / Npos;
                const size_t resRow = (size_t)bb * (Npos + 1) + 1 + (row - bb * Npos);
                #pragma unroll
                for (int j = 0; j < 32; j += 4) {
                    float4 r4 = *(const float4*)(res + resRow * Dd + col + j);
                    v[j] += r4.x; v[j + 1] += r4.y; v[j + 2] += r4.z; v[j + 3] += r4.w;
                }
            }
            if (OUTHL_) {
                #pragma unroll
                for (int j = 0; j < 32; j += 2) {
                    __nv_bfloat16 h0, l0, h1, l1;
                    split_bf(v[j], h0, l0);
                    split_bf(v[j + 1], h1, l1);
                    __nv_bfloat162 ph; ph.x = h0; ph.y = h1;
                    __nv_bfloat162 pl; pl.x = l0; pl.y = l1;
                    *(__nv_bfloat162*)(Ch + (size_t)row * N + col + j) = ph;
                    *(__nv_bfloat162*)(Cl + (size_t)row * N + col + j) = pl;
                }
            } else {
                float* cp = Cf + (size_t)row * N + col;
                #pragma unroll
                for (int j = 0; j < 32; j += 4) {
                    float4 o = make_float4(v[j], v[j + 1], v[j + 2], v[j + 3]);
                    if (ACCUM_) {
                        float4 c4 = *(float4*)(cp + j);
                        o.x += c4.x; o.y += c4.y; o.z += c4.z; o.w += c4.w;
                    }
                    *(float4*)(cp + j) = o;
                }
            }
        }
    }
    __syncthreads();
    if (wid == 0) TC_DEALLOC_CG2(tmem_base, 256);
    CLUSTER_SYNC();
#else
    // ---- generic-target fallback (correct, slow; never runs on sm_103a) ----
    const int tid = threadIdx.x;
    const int rank = blockIdx.x & 1;
    const int rowBase = (blockIdx.x >> 1) * 256 + rank * 128;
    const int colBase = blockIdx.y * 256;
    for (int idx = tid; idx < 128 * 256; idx += 256) {
        const int row = rowBase + (idx >> 8);
        const int col = colBase + (idx & 255);
        if (row >= M) continue;
        float acc = 0.f;
        for (int k = 0; k < K; k++) {
            float a = __bfloat162float(Ah[(size_t)row * K + k])
                    + __bfloat162float(Al[(size_t)row * K + k]);
            float b = __bfloat162float(Bh[(size_t)col * K + k])
                    + __bfloat162float(Bl[(size_t)col * K + k]);
            acc += a * b;
        }
        if (bias) acc += bias[col];
        if (GELU_) acc = gelu_f(acc);
        if (RESMAP_ == 2) {
            const int bb = row / Npos;
            const size_t resRow = (size_t)bb * (Npos + 1) + 1 + (row - bb * Npos);
            acc += res[resRow * Dd + col];
        }
        if (OUTHL_) {
            __nv_bfloat16 h, l; split_bf(acc, h, l);
            Ch[(size_t)row * N + col] = h;
            Cl[(size_t)row * N + col] = l;
        } else {
            if (ACCUM_) acc += Cf[(size_t)row * N + col];
            Cf[(size_t)row * N + col] = acc;
        }
    }
#endif
}

// ---------------- LayerNorm (gathering variants), writes bf16 hi/lo -----------
__global__ __launch_bounds__(256) void ln_kernel(
    int mode, const float* __restrict__ xin, const float* __restrict__ xt2,
    const float* __restrict__ w, const float* __restrict__ b,
    __nv_bfloat16* __restrict__ outh, __nv_bfloat16* __restrict__ outl)
{
    const int row = blockIdx.x;
    const float* src;
    if (mode == 0) {
        src = xin + (size_t)row * Dd;
    } else if (mode == 1) {
        int bb = row / Npos;
        src = xin + ((size_t)bb * (Npos + 1) + 1 + (row - bb * Npos)) * Dd;
    } else {
        int bt = row / SSP, c = row - bt * SSP;
        int bb = bt >> 4, tt = bt & 15;
        if (c == 0) src = xin + (size_t)bb * (Npos + 1) * Dd;
        else        src = xt2 + ((size_t)bb * Npos + (size_t)(c - 1) * Tt + tt) * Dd;
    }
    const int t = threadIdx.x;
    float v0 = src[t], v1 = src[t + 256], v2 = src[t + 512];
    __shared__ float red[8];
    __shared__ float sval;
    float s = v0 + v1 + v2;
    #pragma unroll
    for (int o = 16; o; o >>= 1) s += __shfl_xor_sync(0xffffffffu, s, o);
    if ((t & 31) == 0) red[t >> 5] = s;
    __syncthreads();
    if (t == 0) {
        float tot = 0.f;
        #pragma unroll
        for (int i = 0; i < 8; i++) tot += red[i];
        sval = tot * (1.f / 768.f);
    }
    __syncthreads();
    float mean = sval;
    float d0 = v0 - mean, d1 = v1 - mean, d2 = v2 - mean;
    float q = d0 * d0 + d1 * d1 + d2 * d2;
    #pragma unroll
    for (int o = 16; o; o >>= 1) q += __shfl_xor_sync(0xffffffffu, q, o);
    __syncthreads();
    if ((t & 31) == 0) red[t >> 5] = q;
    __syncthreads();
    if (t == 0) {
        float tot = 0.f;
        #pragma unroll
        for (int i = 0; i < 8; i++) tot += red[i];
        sval = rsqrtf(tot * (1.f / 768.f) + 1e-5f);
    }
    __syncthreads();
    float rstd = sval;
    size_t ob = (size_t)row * Dd;
    #pragma unroll
    for (int u = 0; u < 3; u++) {
        int c = t + u * 256;
        float dv = (u == 0 ? d0 : (u == 1 ? d1 : d2));
        float r = dv * rstd * w[c] + b[c];
        __nv_bfloat16 h, l; split_bf(r, h, l);
        outh[ob + c] = h; outl[ob + c] = l;
    }
}

// ---------------- Temporal attention: T=16, head dim 64 ----------------------
__global__ __launch_bounds__(128) void temporal_attn(
    const float* __restrict__ qkv,
    __nv_bfloat16* __restrict__ outh, __nv_bfloat16* __restrict__ outl)
{
    const int s = blockIdx.x, h = blockIdx.y;
    const int tid = threadIdx.x;
    __shared__ float Q[16][68], K[16][68], V[16][68], P[16][20];
    const float* base = qkv + (size_t)s * Tt * (3 * Dd) + h * HDm;
    for (int i = tid; i < 1024; i += 128) {
        int t = i >> 6, d = i & 63;
        const float* p = base + (size_t)t * (3 * Dd) + d;
        Q[t][d] = p[0] * 0.125f;
        K[t][d] = p[Dd];
        V[t][d] = p[2 * Dd];
    }
    __syncthreads();
    for (int e = tid; e < 256; e += 128) {
        int q = e >> 4, kk = e & 15;
        float sum = 0.f;
        #pragma unroll
        for (int d4 = 0; d4 < 64; d4 += 4) {
            float4 q4 = *reinterpret_cast<const float4*>(&Q[q][d4]);
            float4 k4 = *reinterpret_cast<const float4*>(&K[kk][d4]);
            sum += q4.x * k4.x + q4.y * k4.y + q4.z * k4.z + q4.w * k4.w;
        }
        P[q][kk] = sum;
    }
    __syncthreads();
    if (tid < 16) {
        float mx = -1e30f;
        #pragma unroll
        for (int kk = 0; kk < 16; kk++) mx = fmaxf(mx, P[tid][kk]);
        float sm = 0.f;
        #pragma unroll
        for (int kk = 0; kk < 16; kk++) {
            float p = __expf(P[tid][kk] - mx);
            P[tid][kk] = p; sm += p;
        }
        float inv = 1.f / sm;
        #pragma unroll
        for (int kk = 0; kk < 16; kk++) P[tid][kk] *= inv;
    }
    __syncthreads();
    for (int i = tid; i < 1024; i += 128) {
        int q = i >> 6, d = i & 63;
        float o = 0.f;
        #pragma unroll
        for (int t = 0; t < 16; t++) o += P[q][t] * V[t][d];
        size_t oi = ((size_t)s * Tt + q) * Dd + h * HDm + d;
        __nv_bfloat16 hh, ll; split_bf(o, hh, ll);
        outh[oi] = hh; outl[oi] = ll;
    }
}

// ---------------- Spatial attention: flash-style, S=197, head dim 64 ---------
__global__ __launch_bounds__(128) void spatial_attn(
    const float* __restrict__ qkv,
    __nv_bfloat16* __restrict__ outh, __nv_bfloat16* __restrict__ outl)
{
    const int bh = blockIdx.x;
    const int bt = bh / NHh, h = bh % NHh;
    const int q0 = blockIdx.y * 32;
    const int tid = threadIdx.x;
    constexpr int LD = 72;
    __shared__ float Qs[32][LD], Ks[32][LD], Vs[32][LD], Ps[32][36];

    const float* base = qkv + (size_t)bt * SSP * (3 * Dd) + h * HDm;
    for (int i = tid; i < 2048; i += 128) {
        int r = i >> 6, d = i & 63;
        float v = 0.f;
        if (q0 + r < SSP) v = base[(size_t)(q0 + r) * (3 * Dd) + d] * 0.125f;
        Qs[r][d] = v;
    }
    const int qrow  = tid >> 2;
    const int cbase = (tid & 3) * 8;
    const int dseg  = (tid & 3) * 16;
    float m_i = -1e30f, l_i = 0.f;
    float acc[16];
    #pragma unroll
    for (int u = 0; u < 16; u++) acc[u] = 0.f;

    for (int k0 = 0; k0 < SSP; k0 += 32) {
        __syncthreads();
        for (int i = tid; i < 2048; i += 128) {
            int r = i >> 6, d = i & 63;
            float kv = 0.f, vv = 0.f;
            if (k0 + r < SSP) {
                const float* p = base + (size_t)(k0 + r) * (3 * Dd) + d;
                kv = p[Dd]; vv = p[2 * Dd];
            }
            Ks[r][d] = kv; Vs[r][d] = vv;
        }
        __syncthreads();
        float sreg[8];
        #pragma unroll
        for (int j = 0; j < 8; j++) sreg[j] = 0.f;
        #pragma unroll
        for (int d4 = 0; d4 < 64; d4 += 4) {
            float4 q4 = *reinterpret_cast<const float4*>(&Qs[qrow][d4]);
            #pragma unroll
            for (int j = 0; j < 8; j++) {
                float4 k4 = *reinterpret_cast<const float4*>(&Ks[cbase + j][d4]);
                sreg[j] += q4.x * k4.x + q4.y * k4.y + q4.z * k4.z + q4.w * k4.w;
            }
        }
        float mloc = -1e30f;
        #pragma unroll
        for (int j = 0; j < 8; j++) {
            if (k0 + cbase + j >= SSP) sreg[j] = -1e30f;
            mloc = fmaxf(mloc, sreg[j]);
        }
        mloc = fmaxf(mloc, __shfl_xor_sync(0xffffffffu, mloc, 1));
        mloc = fmaxf(mloc, __shfl_xor_sync(0xffffffffu, mloc, 2));
        float m_new = fmaxf(m_i, mloc);
        float alpha = __expf(m_i - m_new);
        float psum = 0.f;
        #pragma unroll
        for (int j = 0; j < 8; j++) {
            float p = __expf(sreg[j] - m_new);
            Ps[qrow][cbase + j] = p;
            psum += p;
        }
        psum += __shfl_xor_sync(0xffffffffu, psum, 1);
        psum += __shfl_xor_sync(0xffffffffu, psum, 2);
        l_i = l_i * alpha + psum;
        m_i = m_new;
        #pragma unroll
        for (int u = 0; u < 16; u++) acc[u] *= alpha;
        __syncwarp();
        #pragma unroll 4
        for (int kv = 0; kv < 32; kv++) {
            float p = Ps[qrow][kv];
            float4 v0 = *reinterpret_cast<const float4*>(&Vs[kv][dseg]);
            float4 v1 = *reinterpret_cast<const float4*>(&Vs[kv][dseg + 4]);
            float4 v2 = *reinterpret_cast<const float4*>(&Vs[kv][dseg + 8]);
            float4 v3 = *reinterpret_cast<const float4*>(&Vs[kv][dseg + 12]);
            acc[0]  += p * v0.x; acc[1]  += p * v0.y; acc[2]  += p * v0.z; acc[3]  += p * v0.w;
            acc[4]  += p * v1.x; acc[5]  += p * v1.y; acc[6]  += p * v1.z; acc[7]  += p * v1.w;
            acc[8]  += p * v2.x; acc[9]  += p * v2.y; acc[10] += p * v2.z; acc[11] += p * v2.w;
            acc[12] += p * v3.x; acc[13] += p * v3.y; acc[14] += p * v3.z; acc[15] += p * v3.w;
        }
    }
    if (q0 + qrow < SSP) {
        float inv = 1.f / l_i;
        size_t ob = (size_t)(bt * SSP + q0 + qrow) * Dd + h * HDm + dseg;
        #pragma unroll
        for (int u = 0; u < 16; u += 2) {
            __nv_bfloat16 h0, l0, h1, l1;
            split_bf(acc[u] * inv, h0, l0);
            split_bf(acc[u + 1] * inv, h1, l1);
            __nv_bfloat162 ph; ph.x = h0; ph.y = h1;
            __nv_bfloat162 pl; pl.x = l0; pl.y = l1;
            *(__nv_bfloat162*)(outh + ob + u) = ph;
            *(__nv_bfloat162*)(outl + ob + u) = pl;
        }
    }
}

// ---------------- assemble x_new into d_out ----------------------------------
__global__ __launch_bounds__(256) void assemble_k(
    const float* __restrict__ x, const float* __restrict__ xt2,
    const float* __restrict__ rs, float* __restrict__ out)
{
    const int row = blockIdx.x;
    const int b = row / (Npos + 1), c = row - b * (Npos + 1);
    for (int d = threadIdx.x; d < Dd; d += blockDim.x) {
        float v;
        if (c == 0) {
            float sum = 0.f;
            #pragma unroll
            for (int tt = 0; tt < Tt; tt++)
                sum += rs[((size_t)(b * Tt + tt) * SSP) * Dd + d];
            v = x[(size_t)row * Dd + d] + sum * (1.f / 16.f);
        } else {
            int p = c - 1, sidx = p >> 4, tt = p & 15;
            v = xt2[((size_t)b * Npos + p) * Dd + d]
              + rs[((size_t)(b * Tt + tt) * SSP + 1 + sidx) * Dd + d];
        }
        out[(size_t)row * Dd + d] = v;
    }
}

// ---------------- launch ------------------------------------------------------
extern "C" void kernel_launch(void* const* d_in, const int* in_sizes, int n_in,
                              void* d_out, int out_size)
{
    (void)in_sizes; (void)n_in; (void)out_size;
    const float* x        = (const float*)d_in[0];
    const float* tn1_w    = (const float*)d_in[1];
    const float* tn1_b    = (const float*)d_in[2];
    const float* t_qkv_w  = (const float*)d_in[3];
    const float* t_proj_w = (const float*)d_in[4];
    const float* t_proj_b = (const float*)d_in[5];
    const float* tfc_w    = (const float*)d_in[6];
    const float* tfc_b    = (const float*)d_in[7];
    const float* n1_w     = (const float*)d_in[8];
    const float* n1_b     = (const float*)d_in[9];
    const float* s_qkv_w  = (const float*)d_in[10];
    const float* s_proj_w = (const float*)d_in[11];
    const float* s_proj_b = (const float*)d_in[12];
    const float* n2_w     = (const float*)d_in[13];
    const float* n2_b     = (const float*)d_in[14];
    const float* fc1_w    = (const float*)d_in[15];
    const float* fc1_b    = (const float*)d_in[16];
    const float* fc2_w    = (const float*)d_in[17];
    const float* fc2_b    = (const float*)d_in[18];
    float* out = (float*)d_out;

    float *qkv, *xt2, *rs;
    __nv_bfloat16 *lnh, *lnl, *atth, *attl, *tmph, *tmpl, *hidh, *hidl, *wh, *wl;
    cudaGetSymbolAddress((void**)&qkv,  g_qkv);
    cudaGetSymbolAddress((void**)&xt2,  g_xt2);
    cudaGetSymbolAddress((void**)&rs,   g_rs);
    cudaGetSymbolAddress((void**)&lnh,  g_lnh);
    cudaGetSymbolAddress((void**)&lnl,  g_lnl);
    cudaGetSymbolAddress((void**)&atth, g_atth);
    cudaGetSymbolAddress((void**)&attl, g_attl);
    cudaGetSymbolAddress((void**)&tmph, g_tmph);
    cudaGetSymbolAddress((void**)&tmpl, g_tmpl);
    cudaGetSymbolAddress((void**)&hidh, g_hidh);
    cudaGetSymbolAddress((void**)&hidl, g_hidl);
    cudaGetSymbolAddress((void**)&wh,   g_wh);
    cudaGetSymbolAddress((void**)&wl,   g_wl);

    // pad + header + 2 stages of 64KB
    const size_t SMEMSZ = 1024 + 1024 + 2 * 65536;
    cudaFuncSetAttribute(mma_gemm<0,0,0,0>, cudaFuncAttributeMaxDynamicSharedMemorySize, SMEMSZ);
    cudaFuncSetAttribute(mma_gemm<0,0,0,1>, cudaFuncAttributeMaxDynamicSharedMemorySize, SMEMSZ);
    cudaFuncSetAttribute(mma_gemm<0,2,0,0>, cudaFuncAttributeMaxDynamicSharedMemorySize, SMEMSZ);
    cudaFuncSetAttribute(mma_gemm<1,0,0,1>, cudaFuncAttributeMaxDynamicSharedMemorySize, SMEMSZ);
    cudaFuncSetAttribute(mma_gemm<0,0,1,0>, cudaFuncAttributeMaxDynamicSharedMemorySize, SMEMSZ);

    // 0. weight transpose + hi/lo split
    wsplit<<<dim3(2304/32, 768/32), 256>>>(t_qkv_w,  768, 2304, wh + OFF_TQKV,  wl + OFF_TQKV);
    wsplit<<<dim3( 768/32, 768/32), 256>>>(t_proj_w, 768,  768, wh + OFF_TPROJ, wl + OFF_TPROJ);
    wsplit<<<dim3( 768/32, 768/32), 256>>>(tfc_w,    768,  768, wh + OFF_TFC,   wl + OFF_TFC);
    wsplit<<<dim3(2304/32, 768/32), 256>>>(s_qkv_w,  768, 2304, wh + OFF_SQKV,  wl + OFF_SQKV);
    wsplit<<<dim3( 768/32, 768/32), 256>>>(s_proj_w, 768,  768, wh + OFF_SPROJ, wl + OFF_SPROJ);
    wsplit<<<dim3(3072/32, 768/32), 256>>>(fc1_w,    768, 3072, wh + OFF_FC1,   wl + OFF_FC1);
    wsplit<<<dim3( 768/32, 3072/32), 256>>>(fc2_w,  3072,  768, wh + OFF_FC2,   wl + OFF_FC2);

    // M tiles of 256 (x2 cluster CTAs): NTOK_T -> 98, NTOK_S -> 99, NROWS -> 99
    // 1. temporal LN
    ln_kernel<<<NTOK_T, 256>>>(1, x, nullptr, tn1_w, tn1_b, lnh, lnl);
    // 2. temporal QKV -> f32
    mma_gemm<0,0,0,0><<<dim3(196, 9), 256, SMEMSZ>>>(NTOK_T, 2304, 768,
        lnh, lnl, wh + OFF_TQKV, wl + OFF_TQKV, nullptr, nullptr, qkv, nullptr, nullptr);
    // 3. temporal attention -> hi/lo
    temporal_attn<<<dim3(SEQT, NHh), 128>>>(qkv, atth, attl);
    // 4. temporal proj (+bias) -> hi/lo
    mma_gemm<0,0,0,1><<<dim3(196, 3), 256, SMEMSZ>>>(NTOK_T, 768, 768,
        atth, attl, wh + OFF_TPROJ, wl + OFF_TPROJ, t_proj_b, nullptr, nullptr, tmph, tmpl);
    // 5. tfc (+bias) + residual x (cls-skip) -> xt2 f32
    mma_gemm<0,2,0,0><<<dim3(196, 3), 256, SMEMSZ>>>(NTOK_T, 768, 768,
        tmph, tmpl, wh + OFF_TFC, wl + OFF_TFC, tfc_b, x, xt2, nullptr, nullptr);
    // 6. spatial LN (gather)
    ln_kernel<<<NTOK_S, 256>>>(2, x, xt2, n1_w, n1_b, lnh, lnl);
    // 7. spatial QKV -> f32
    mma_gemm<0,0,0,0><<<dim3(198, 9), 256, SMEMSZ>>>(NTOK_S, 2304, 768,
        lnh, lnl, wh + OFF_SQKV, wl + OFF_SQKV, nullptr, nullptr, qkv, nullptr, nullptr);
    // 8. spatial attention -> hi/lo
    spatial_attn<<<dim3(BT * NHh, 7), 128>>>(qkv, atth, attl);
    // 9. spatial proj (+bias) -> rs f32
    mma_gemm<0,0,0,0><<<dim3(198, 3), 256, SMEMSZ>>>(NTOK_S, 768, 768,
        atth, attl, wh + OFF_SPROJ, wl + OFF_SPROJ, s_proj_b, nullptr, rs, nullptr, nullptr);
    // 10. assemble x_new -> d_out
    assemble_k<<<NROWS, 256>>>(x, xt2, rs, out);
    // 11. final LN
    ln_kernel<<<NROWS, 256>>>(0, out, nullptr, n2_w, n2_b, lnh, lnl);
    // 12. fc1 (+bias, gelu) -> hi/lo
    mma_gemm<1,0,0,1><<<dim3(198, 12), 256, SMEMSZ>>>(NROWS, 3072, 768,
        lnh, lnl, wh + OFF_FC1, wl + OFF_FC1, fc1_b, nullptr, nullptr, hidh, hidl);
    // 13. fc2 (+bias), accumulate into d_out
    mma_gemm<0,0,1,0><<<dim3(198, 3), 256, SMEMSZ>>>(NROWS, 768, 3072,
        hidh, hidl, wh + OFF_FC2, wl + OFF_FC2, fc2_b, nullptr, out, nullptr, nullptr);
}

// round 11
// speedup vs baseline: 1.0072x; 1.0072x over previous
#include <cuda_runtime.h>
#include <cuda_bf16.h>
#include <cstdint>

// Problem constants
#define Bn    8
#define Tt    16
#define Dd    768
#define NHh   12
#define HDm   64
#define HIDd  3072
#define HW    196
#define Npos  3136
#define SEQT  1568
#define NTOK_T 25088
#define BT    128
#define SSP   197
#define NTOK_S 25216
#define NROWS 25096

// tcgen05 is arch-accelerated: legal only in the sm_103a-specific pass.
#if defined(__CUDA_ARCH_FEAT_SM103_ALL)
#define TC_OK 1
#elif defined(__CUDA_ARCH_SPECIFIC__) && (__CUDA_ARCH_SPECIFIC__ == 1030)
#define TC_OK 1
#else
#define TC_OK 0
#endif

// ---------------- scratch (device globals; no runtime alloc) ----------------
__device__ __align__(16) float g_qkv[(size_t)NTOK_S * 3 * Dd];
__device__ __align__(16) __nv_bfloat16 g_hidh[(size_t)NROWS * HIDd];
__device__ __align__(16) __nv_bfloat16 g_hidl[(size_t)NROWS * HIDd];
__device__ __align__(16) __nv_bfloat16 g_lnh[(size_t)NTOK_S * Dd];
__device__ __align__(16) __nv_bfloat16 g_lnl[(size_t)NTOK_S * Dd];
__device__ __align__(16) __nv_bfloat16 g_atth[(size_t)NTOK_S * Dd];
__device__ __align__(16) __nv_bfloat16 g_attl[(size_t)NTOK_S * Dd];
__device__ __align__(16) __nv_bfloat16 g_tmph[(size_t)NTOK_T * Dd];
__device__ __align__(16) __nv_bfloat16 g_tmpl[(size_t)NTOK_T * Dd];
__device__ __align__(16) float g_xt2[(size_t)NTOK_T * Dd];
__device__ __align__(16) float g_rs [(size_t)NTOK_S * Dd];
#define WTOT 10027008
__device__ __align__(16) __nv_bfloat16 g_wh[WTOT];
__device__ __align__(16) __nv_bfloat16 g_wl[WTOT];
#define OFF_TQKV  0
#define OFF_TPROJ 1769472
#define OFF_TFC   2359296
#define OFF_SQKV  2949120
#define OFF_SPROJ 4718592
#define OFF_FC1   5308416
#define OFF_FC2   7667712

// ---------------- helpers -----------------------------------------------------
__device__ __forceinline__ float gelu_f(float v) {
    return 0.5f * v * (1.0f + erff(v * 0.70710678118654752f));
}
__device__ __forceinline__ void split_bf(float v, __nv_bfloat16& h, __nv_bfloat16& l) {
    h = __float2bfloat16(v);
    l = __float2bfloat16(v - __bfloat162float(h));
}
__device__ __forceinline__ uint32_t smem_u32(const void* p) {
    uint32_t a;
    asm("{ .reg .u64 t; cvta.to.shared.u64 t, %1; cvt.u32.u64 %0, t; }" : "=r"(a) : "l"(p));
    return a;
}
__device__ __forceinline__ uint32_t elect_one() {
    uint32_t p;
    asm volatile("{\n\t.reg .pred p;\n\telect.sync _|p, 0xFFFFFFFF;\n\tselp.b32 %0, 1, 0, p;\n\t}" : "=r"(p));
    return p;
}
__device__ __forceinline__ uint32_t ctarank() {
    uint32_t r;
    asm("mov.u32 %0, %%cluster_ctarank;" : "=r"(r));
    return r;
}
// cp.async 16B with zero-fill predication (src_size 0 -> no read, zeros)
__device__ __forceinline__ void cp16(uint32_t dst, const void* src, uint32_t srcsz) {
    asm volatile("cp.async.cg.shared.global [%0], [%1], 16, %2;"
        :: "r"(dst), "l"(src), "r"(srcsz) : "memory");
}
#define CP_COMMIT() asm volatile("cp.async.commit_group;" ::: "memory")
#define CP_WAIT0()  asm volatile("cp.async.wait_group 0;" ::: "memory")

#define SWZ(b) ((b) ^ (((b) >> 3) & 0x70))

static constexpr uint64_t DESC_SW128 =
    (2ull << 61) | (1ull << 46) | (64ull << 32) | (1ull << 16);
__device__ __forceinline__ uint64_t mkdesc(uint32_t addr) {
    return DESC_SW128 | ((uint64_t)(addr >> 4) & 0x3FFF);
}

#define CLUSTER_SYNC() do { \
    asm volatile("barrier.cluster.arrive.aligned;" ::: "memory"); \
    asm volatile("barrier.cluster.wait.aligned;" ::: "memory"); } while (0)

#define MBAR_INIT(a, c) \
    asm volatile("mbarrier.init.shared.b64 [%0], %1;" :: "r"((uint32_t)(a)), "r"((uint32_t)(c)) : "memory")

#define MBAR_ARRIVE_RANK0(a) do { uint32_t _ra; \
    asm volatile("mapa.shared::cluster.u32 %0, %1, %2;" : "=r"(_ra) : "r"((uint32_t)(a)), "r"(0)); \
    asm volatile("mbarrier.arrive.shared::cluster.b64 _, [%0];" :: "r"(_ra) : "memory"); } while (0)

#define MBAR_WAIT(a, ph) do { \
    uint32_t _m = (uint32_t)(a), _p = (uint32_t)(ph), _d; \
    asm volatile("{\n\t.reg .pred p;\n\t" \
        "mbarrier.try_wait.parity.acquire.cta.shared::cta.b64 p, [%1], %2;\n\t" \
        "selp.b32 %0, 1, 0, p;\n\t}" : "=r"(_d) : "r"(_m), "r"(_p) : "memory"); \
    if (!_d) { \
        asm volatile("{\n\t.reg .pred P1;\n\t" \
            "WL_%=:\n\t" \
            "mbarrier.try_wait.parity.acquire.cta.shared::cta.b64 P1, [%0], %1, 0x989680;\n\t" \
            "@P1 bra.uni WD_%=;\n\t" \
            "bra.uni WL_%=;\n\t" \
            "WD_%=:\n\t}" :: "r"(_m), "r"(_p) : "memory"); \
    } \
} while (0)

#define MBAR_WAIT_CLU(a, ph) do { \
    uint32_t _m = (uint32_t)(a), _p = (uint32_t)(ph), _d; \
    asm volatile("{\n\t.reg .pred p;\n\t" \
        "mbarrier.try_wait.parity.acquire.cluster.shared::cta.b64 p, [%1], %2;\n\t" \
        "selp.b32 %0, 1, 0, p;\n\t}" : "=r"(_d) : "r"(_m), "r"(_p) : "memory"); \
    if (!_d) { \
        asm volatile("{\n\t.reg .pred P1;\n\t" \
            "WL_%=:\n\t" \
            "mbarrier.try_wait.parity.acquire.cluster.shared::cta.b64 P1, [%0], %1, 0x989680;\n\t" \
            "@P1 bra.uni WD_%=;\n\t" \
            "bra.uni WL_%=;\n\t" \
            "WD_%=:\n\t}" :: "r"(_m), "r"(_p) : "memory"); \
    } \
} while (0)

#if TC_OK
#define TC_ALLOC_CG2(smem_addr, n) \
    asm volatile("tcgen05.alloc.cta_group::2.sync.aligned.shared::cta.b32 [%0], %1;" \
        :: "r"((uint32_t)(smem_addr)), "r"((uint32_t)(n)) : "memory")
#define TC_DEALLOC_CG2(tm, n) \
    asm volatile("tcgen05.dealloc.cta_group::2.sync.aligned.b32 %0, %1;" :: "r"(tm), "r"((uint32_t)(n)))
#define TC_RELINQ_CG2() \
    asm volatile("tcgen05.relinquish_alloc_permit.cta_group::2.sync.aligned;")
#define TC_FENCE_AFTER()  asm volatile("tcgen05.fence::after_thread_sync;" ::: "memory")
#define TC_WAIT_LD()      asm volatile("tcgen05.wait::ld.sync.aligned;" ::: "memory")
#define TC_COMMIT_MC2(mbar) \
    asm volatile("tcgen05.commit.cta_group::2.mbarrier::arrive::one.shared::cluster.multicast::cluster.b64 [%0], %1;" \
        :: "r"((uint32_t)(mbar)), "h"((uint16_t)3) : "memory")

#define TC_LD_X32(r, tm) \
    asm volatile("tcgen05.ld.sync.aligned.32x32b.x32.b32 " \
        "{%0, %1, %2, %3, %4, %5, %6, %7, %8, %9, %10, %11, %12, %13, %14, %15, " \
        " %16, %17, %18, %19, %20, %21, %22, %23, %24, %25, %26, %27, %28, %29, %30, %31}, [%32];" \
        : "=r"((r)[0]),  "=r"((r)[1]),  "=r"((r)[2]),  "=r"((r)[3]), \
          "=r"((r)[4]),  "=r"((r)[5]),  "=r"((r)[6]),  "=r"((r)[7]), \
          "=r"((r)[8]),  "=r"((r)[9]),  "=r"((r)[10]), "=r"((r)[11]), \
          "=r"((r)[12]), "=r"((r)[13]), "=r"((r)[14]), "=r"((r)[15]), \
          "=r"((r)[16]), "=r"((r)[17]), "=r"((r)[18]), "=r"((r)[19]), \
          "=r"((r)[20]), "=r"((r)[21]), "=r"((r)[22]), "=r"((r)[23]), \
          "=r"((r)[24]), "=r"((r)[25]), "=r"((r)[26]), "=r"((r)[27]), \
          "=r"((r)[28]), "=r"((r)[29]), "=r"((r)[30]), "=r"((r)[31]) \
        : "r"(tm))

__device__ __forceinline__ void mma_f16_ss_cg2(uint32_t d, uint64_t a, uint64_t b,
                                               uint32_t idesc, uint32_t en) {
    asm volatile("{\n\t.reg .pred p;\n\tsetp.ne.u32 p, %5, 0;\n\t"
        "tcgen05.mma.cta_group::2.kind::f16 [%0], %1, %2, %3, "
        "{%4, %4, %4, %4, %4, %4, %4, %4}, p;\n\t}"
        :: "r"(d), "l"(a), "l"(b), "r"(idesc), "r"(0u), "r"(en) : "memory");
}
#endif  // TC_OK

// ---------------- all weights: transpose + hi/lo split, ONE launch ------------
// tiles: tqkv 24x72=1728 | tproj 576 | tfc 576 | sqkv 1728 | sproj 576
//        fc1 24x96=2304 | fc2 96x24=2304   -> total 9792
__global__ __launch_bounds__(256) void wsplit_all(
    const float* w0, const float* w1, const float* w2, const float* w3,
    const float* w4, const float* w5, const float* w6,
    __nv_bfloat16* __restrict__ Wh, __nv_bfloat16* __restrict__ Wl)
{
    int id = blockIdx.x;
    const float* W; int K, N, nt; size_t off;
    if      (id < 1728) {                     W = w0; K = 768;  N = 2304; nt = 72; off = OFF_TQKV; }
    else if (id < 2304) { id -= 1728;         W = w1; K = 768;  N = 768;  nt = 24; off = OFF_TPROJ; }
    else if (id < 2880) { id -= 2304;         W = w2; K = 768;  N = 768;  nt = 24; off = OFF_TFC; }
    else if (id < 4608) { id -= 2880;         W = w3; K = 768;  N = 2304; nt = 72; off = OFF_SQKV; }
    else if (id < 5184) { id -= 4608;         W = w4; K = 768;  N = 768;  nt = 24; off = OFF_SPROJ; }
    else if (id < 7488) { id -= 5184;         W = w5; K = 768;  N = 3072; nt = 96; off = OFF_FC1; }
    else                { id -= 7488;         W = w6; K = 3072; N = 768;  nt = 24; off = OFF_FC2; }
    const int n0 = (id % nt) * 32, k0 = (id / nt) * 32;

    __shared__ float t[32][33];
    const int lx = threadIdx.x & 31, ly = threadIdx.x >> 5;
    #pragma unroll
    for (int i = ly; i < 32; i += 8)
        t[i][lx] = W[(size_t)(k0 + i) * N + n0 + lx];
    __syncthreads();
    #pragma unroll
    for (int i = ly; i < 32; i += 8) {
        float v = t[lx][i];
        size_t o = off + (size_t)(n0 + i) * K + k0 + lx;
        __nv_bfloat16 h, l; split_bf(v, h, l);
        Wh[o] = h; Wl[o] = l;
    }
}

// ---------------- GEMM: C[M,N] = (Ah+Al)[M,K] @ (Bh+Bl)^T[K,N] -----------------
// cg2 2-CTA cooperative MMA: 256x256 tile per pair, BK=64, 3-stage cp.async
// ring buffer, 3-pass bf16 error compensation.
template<int GELU_, int RESMAP_, int ACCUM_, int OUTHL_>
__global__ __launch_bounds__(256, 1) __cluster_dims__(2, 1, 1)
void mma_gemm(
    int M, int N, int K,
    const __nv_bfloat16* __restrict__ Ah, const __nv_bfloat16* __restrict__ Al,
    const __nv_bfloat16* __restrict__ Bh, const __nv_bfloat16* __restrict__ Bl,
    const float* __restrict__ bias, const float* __restrict__ res,
    float* __restrict__ Cf,
    __nv_bfloat16* __restrict__ Ch, __nv_bfloat16* __restrict__ Cl)
{
#if TC_OK
    extern __shared__ char dsm[];
    const uint32_t raw = smem_u32(dsm);
    const uint32_t pad = (1024u - (raw & 1023u)) & 1023u;
    const uint32_t sb32 = raw + pad;

    const int tid = threadIdx.x;
    const int wid = tid >> 5, lane = tid & 31;
    const uint32_t rank = ctarank();
    const int tileM = blockIdx.x >> 1;
    const int rowBase = tileM * 256 + (int)rank * 128;
    const int colBase = blockIdx.y * 256;
    const int bRow0   = colBase + (int)rank * 128;

    // header: [0] tmem ptr; ready[b] @16+8b (b=0..2, count=2, on rank0);
    //         done[b] @48+8b (count=1, per-CTA via multicast commit)
    if (wid == 0) {
        TC_ALLOC_CG2(sb32, 256);
        TC_RELINQ_CG2();
    }
    if (tid == 0) {
        #pragma unroll
        for (int b = 0; b < 3; b++) {
            MBAR_INIT(sb32 + 16 + b * 8, 2);
            MBAR_INIT(sb32 + 48 + b * 8, 1);
        }
    }
    __syncthreads();
    uint32_t tmem_base;
    asm volatile("ld.shared.b32 %0, [%1];" : "=r"(tmem_base) : "r"(sb32));
    CLUSTER_SYNC();

    // buffers: 1024 + b*65536 ; Ah +0, Al +16384, Bh +32768, Bl +49152
    auto fill = [&](int buf, int k0) {
        const uint32_t sbb = sb32 + 1024 + buf * 65536;
        const size_t kb = (size_t)k0 * 2;
        #pragma unroll
        for (int it = 0; it < 4; it++) {
            int idx = it * 256 + tid;
            int r = idx >> 3, cc = (idx & 7) * 16;
            uint32_t so = SWZ(r * 128 + cc);
            int grow = rowBase + r;
            uint32_t asz = (grow < M) ? 16u : 0u;
            size_t go = (size_t)grow * K * 2 + kb + cc;
            cp16(sbb + so,         (const char*)Ah + go, asz);
            cp16(sbb + 16384 + so, (const char*)Al + go, asz);
            size_t gb = (size_t)(bRow0 + r) * K * 2 + kb + cc;
            cp16(sbb + 32768 + so, (const char*)Bh + gb, 16u);
            cp16(sbb + 49152 + so, (const char*)Bl + gb, 16u);
        }
        CP_COMMIT();
        CP_WAIT0();
        __syncthreads();
        if (tid == 0) {
            asm volatile("fence.proxy.async;" ::: "memory");
            MBAR_ARRIVE_RANK0(sb32 + 16 + buf * 8);
        }
    };

    const uint32_t idesc = (1u << 4) | (1u << 7) | (1u << 10)
                         | ((256u / 8) << 17) | ((256u / 16) << 24);
    const int nStages = K / 64;

    fill(0, 0);
    if (nStages > 1) fill(1, 64);

    int rph[3] = {0, 0, 0};
    int dph[3] = {0, 0, 0};
    for (int s = 0; s < nStages; s++) {
        const int buf = s % 3;
        if (rank == 0 && wid == 0) {
            if (elect_one()) {
                MBAR_WAIT_CLU(sb32 + 16 + buf * 8, rph[buf]);
                rph[buf] ^= 1;
                const uint32_t tb32 = sb32 + 1024 + buf * 65536;
                const uint64_t dAh = mkdesc(tb32);
                const uint64_t dAl = mkdesc(tb32 + 16384);
                const uint64_t dBh = mkdesc(tb32 + 32768);
                const uint64_t dBl = mkdesc(tb32 + 49152);
                #pragma unroll
                for (int p = 0; p < 3; p++) {
                    const uint64_t da = (p == 1) ? dAl : dAh;
                    const uint64_t db = (p == 2) ? dBl : dBh;
                    #pragma unroll
                    for (int k16 = 0; k16 < 4; k16++)
                        mma_f16_ss_cg2(tmem_base, da + 2 * k16, db + 2 * k16, idesc,
                                       (s > 0) || (p > 0) || (k16 > 0));
                }
                TC_COMMIT_MC2(sb32 + 48 + buf * 8);
            }
        }
        // fill two stages ahead while MMA s runs
        if (s + 2 < nStages) {
            const int fb = (s + 2) % 3;     // == (s-1)%3
            if (s >= 1) {                    // buffer last used by MMA stage s-1
                MBAR_WAIT(sb32 + 48 + fb * 8, dph[fb]);
                dph[fb] ^= 1;
            }
            fill(fb, (s + 2) * 64);
        }
    }
    {
        const int lb = (nStages - 1) % 3;
        MBAR_WAIT(sb32 + 48 + lb * 8, dph[lb]);
    }
    TC_FENCE_AFTER();

    // ---- epilogue: this CTA's 128 rows x 256 cols in its own TMEM
    const int w4 = wid & 3;
    const int whalf = (wid >> 2) * 128;
    const int row = rowBase + w4 * 32 + lane;
    const bool valid = row < M;
    for (int c0 = 0; c0 < 128; c0 += 32) {
        uint32_t r32[32];
        TC_LD_X32(r32, tmem_base + whalf + c0);
        TC_WAIT_LD();
        if (valid) {
            const int col = colBase + whalf + c0;
            float v[32];
            #pragma unroll
            for (int j = 0; j < 32; j++) {
                v[j] = __uint_as_float(r32[j]);
                if (bias) v[j] += bias[col + j];
                if (GELU_) v[j] = gelu_f(v[j]);
            }
            if (RESMAP_ == 2) {
                const int bb = row / Npos;
                const size_t resRow = (size_t)bb * (Npos + 1) + 1 + (row - bb * Npos);
                #pragma unroll
                for (int j = 0; j < 32; j += 4) {
                    float4 r4 = *(const float4*)(res + resRow * Dd + col + j);
                    v[j] += r4.x; v[j + 1] += r4.y; v[j + 2] += r4.z; v[j + 3] += r4.w;
                }
            }
            if (OUTHL_) {
                #pragma unroll
                for (int j = 0; j < 32; j += 2) {
                    __nv_bfloat16 h0, l0, h1, l1;
                    split_bf(v[j], h0, l0);
                    split_bf(v[j + 1], h1, l1);
                    __nv_bfloat162 ph; ph.x = h0; ph.y = h1;
                    __nv_bfloat162 pl; pl.x = l0; pl.y = l1;
                    *(__nv_bfloat162*)(Ch + (size_t)row * N + col + j) = ph;
                    *(__nv_bfloat162*)(Cl + (size_t)row * N + col + j) = pl;
                }
            } else {
                float* cp = Cf + (size_t)row * N + col;
                #pragma unroll
                for (int j = 0; j < 32; j += 4) {
                    float4 o = make_float4(v[j], v[j + 1], v[j + 2], v[j + 3]);
                    if (ACCUM_) {
                        float4 c4 = *(float4*)(cp + j);
                        o.x += c4.x; o.y += c4.y; o.z += c4.z; o.w += c4.w;
                    }
                    *(float4*)(cp + j) = o;
                }
            }
        }
    }
    __syncthreads();
    if (wid == 0) TC_DEALLOC_CG2(tmem_base, 256);
    CLUSTER_SYNC();
#else
    // ---- generic-target fallback (correct, slow; never runs on sm_103a) ----
    const int tid = threadIdx.x;
    const int rank = blockIdx.x & 1;
    const int rowBase = (blockIdx.x >> 1) * 256 + rank * 128;
    const int colBase = blockIdx.y * 256;
    for (int idx = tid; idx < 128 * 256; idx += 256) {
        const int row = rowBase + (idx >> 8);
        const int col = colBase + (idx & 255);
        if (row >= M) continue;
        float acc = 0.f;
        for (int k = 0; k < K; k++) {
            float a = __bfloat162float(Ah[(size_t)row * K + k])
                    + __bfloat162float(Al[(size_t)row * K + k]);
            float b = __bfloat162float(Bh[(size_t)col * K + k])
                    + __bfloat162float(Bl[(size_t)col * K + k]);
            acc += a * b;
        }
        if (bias) acc += bias[col];
        if (GELU_) acc = gelu_f(acc);
        if (RESMAP_ == 2) {
            const int bb = row / Npos;
            const size_t resRow = (size_t)bb * (Npos + 1) + 1 + (row - bb * Npos);
            acc += res[resRow * Dd + col];
        }
        if (OUTHL_) {
            __nv_bfloat16 h, l; split_bf(acc, h, l);
            Ch[(size_t)row * N + col] = h;
            Cl[(size_t)row * N + col] = l;
        } else {
            if (ACCUM_) acc += Cf[(size_t)row * N + col];
            Cf[(size_t)row * N + col] = acc;
        }
    }
#endif
}

// ---------------- LayerNorm (gathering variants), writes bf16 hi/lo -----------
__global__ __launch_bounds__(256) void ln_kernel(
    int mode, const float* __restrict__ xin, const float* __restrict__ xt2,
    const float* __restrict__ w, const float* __restrict__ b,
    __nv_bfloat16* __restrict__ outh, __nv_bfloat16* __restrict__ outl)
{
    const int row = blockIdx.x;
    const float* src;
    if (mode == 0) {
        src = xin + (size_t)row * Dd;
    } else if (mode == 1) {
        int bb = row / Npos;
        src = xin + ((size_t)bb * (Npos + 1) + 1 + (row - bb * Npos)) * Dd;
    } else {
        int bt = row / SSP, c = row - bt * SSP;
        int bb = bt >> 4, tt = bt & 15;
        if (c == 0) src = xin + (size_t)bb * (Npos + 1) * Dd;
        else        src = xt2 + ((size_t)bb * Npos + (size_t)(c - 1) * Tt + tt) * Dd;
    }
    const int t = threadIdx.x;
    float v0 = src[t], v1 = src[t + 256], v2 = src[t + 512];
    __shared__ float red[8];
    __shared__ float sval;
    float s = v0 + v1 + v2;
    #pragma unroll
    for (int o = 16; o; o >>= 1) s += __shfl_xor_sync(0xffffffffu, s, o);
    if ((t & 31) == 0) red[t >> 5] = s;
    __syncthreads();
    if (t == 0) {
        float tot = 0.f;
        #pragma unroll
        for (int i = 0; i < 8; i++) tot += red[i];
        sval = tot * (1.f / 768.f);
    }
    __syncthreads();
    float mean = sval;
    float d0 = v0 - mean, d1 = v1 - mean, d2 = v2 - mean;
    float q = d0 * d0 + d1 * d1 + d2 * d2;
    #pragma unroll
    for (int o = 16; o; o >>= 1) q += __shfl_xor_sync(0xffffffffu, q, o);
    __syncthreads();
    if ((t & 31) == 0) red[t >> 5] = q;
    __syncthreads();
    if (t == 0) {
        float tot = 0.f;
        #pragma unroll
        for (int i = 0; i < 8; i++) tot += red[i];
        sval = rsqrtf(tot * (1.f / 768.f) + 1e-5f);
    }
    __syncthreads();
    float rstd = sval;
    size_t ob = (size_t)row * Dd;
    #pragma unroll
    for (int u = 0; u < 3; u++) {
        int c = t + u * 256;
        float dv = (u == 0 ? d0 : (u == 1 ? d1 : d2));
        float r = dv * rstd * w[c] + b[c];
        __nv_bfloat16 h, l; split_bf(r, h, l);
        outh[ob + c] = h; outl[ob + c] = l;
    }
}

// ---------------- fused assemble x_new -> d_out + final LN -> hi/lo ----------
__global__ __launch_bounds__(256) void assemble_ln(
    const float* __restrict__ x, const float* __restrict__ xt2,
    const float* __restrict__ rs,
    const float* __restrict__ w, const float* __restrict__ b,
    float* __restrict__ out,
    __nv_bfloat16* __restrict__ outh, __nv_bfloat16* __restrict__ outl)
{
    const int row = blockIdx.x;
    const int bb = row / (Npos + 1), c = row - bb * (Npos + 1);
    const int t = threadIdx.x;
    float v[3];
    if (c == 0) {
        #pragma unroll
        for (int u = 0; u < 3; u++) {
            int d = t + u * 256;
            float sum = 0.f;
            #pragma unroll
            for (int tt = 0; tt < Tt; tt++)
                sum += rs[((size_t)(bb * Tt + tt) * SSP) * Dd + d];
            v[u] = x[(size_t)row * Dd + d] + sum * (1.f / 16.f);
        }
    } else {
        int p = c - 1, sidx = p >> 4, tt = p & 15;
        const float* xr = xt2 + ((size_t)bb * Npos + p) * Dd;
        const float* rr = rs + ((size_t)(bb * Tt + tt) * SSP + 1 + sidx) * Dd;
        #pragma unroll
        for (int u = 0; u < 3; u++) {
            int d = t + u * 256;
            v[u] = xr[d] + rr[d];
        }
    }
    float* op = out + (size_t)row * Dd;
    op[t] = v[0]; op[t + 256] = v[1]; op[t + 512] = v[2];

    // LN over v
    __shared__ float red[8];
    __shared__ float sval;
    float s = v[0] + v[1] + v[2];
    #pragma unroll
    for (int o = 16; o; o >>= 1) s += __shfl_xor_sync(0xffffffffu, s, o);
    if ((t & 31) == 0) red[t >> 5] = s;
    __syncthreads();
    if (t == 0) {
        float tot = 0.f;
        #pragma unroll
        for (int i = 0; i < 8; i++) tot += red[i];
        sval = tot * (1.f / 768.f);
    }
    __syncthreads();
    float mean = sval;
    float d0 = v[0] - mean, d1 = v[1] - mean, d2 = v[2] - mean;
    float q = d0 * d0 + d1 * d1 + d2 * d2;
    #pragma unroll
    for (int o = 16; o; o >>= 1) q += __shfl_xor_sync(0xffffffffu, q, o);
    __syncthreads();
    if ((t & 31) == 0) red[t >> 5] = q;
    __syncthreads();
    if (t == 0) {
        float tot = 0.f;
        #pragma unroll
        for (int i = 0; i < 8; i++) tot += red[i];
        sval = rsqrtf(tot * (1.f / 768.f) + 1e-5f);
    }
    __syncthreads();
    float rstd = sval;
    size_t ob = (size_t)row * Dd;
    float dv[3] = {d0, d1, d2};
    #pragma unroll
    for (int u = 0; u < 3; u++) {
        int cc = t + u * 256;
        float r = dv[u] * rstd * w[cc] + b[cc];
        __nv_bfloat16 h, l; split_bf(r, h, l);
        outh[ob + cc] = h; outl[ob + cc] = l;
    }
}

// ---------------- Temporal attention: T=16, head dim 64 ----------------------
__global__ __launch_bounds__(128) void temporal_attn(
    const float* __restrict__ qkv,
    __nv_bfloat16* __restrict__ outh, __nv_bfloat16* __restrict__ outl)
{
    const int s = blockIdx.x, h = blockIdx.y;
    const int tid = threadIdx.x;
    __shared__ float Q[16][68], K[16][68], V[16][68], P[16][20];
    const float* base = qkv + (size_t)s * Tt * (3 * Dd) + h * HDm;
    for (int i = tid; i < 1024; i += 128) {
        int t = i >> 6, d = i & 63;
        const float* p = base + (size_t)t * (3 * Dd) + d;
        Q[t][d] = p[0] * 0.125f;
        K[t][d] = p[Dd];
        V[t][d] = p[2 * Dd];
    }
    __syncthreads();
    for (int e = tid; e < 256; e += 128) {
        int q = e >> 4, kk = e & 15;
        float sum = 0.f;
        #pragma unroll
        for (int d4 = 0; d4 < 64; d4 += 4) {
            float4 q4 = *reinterpret_cast<const float4*>(&Q[q][d4]);
            float4 k4 = *reinterpret_cast<const float4*>(&K[kk][d4]);
            sum += q4.x * k4.x + q4.y * k4.y + q4.z * k4.z + q4.w * k4.w;
        }
        P[q][kk] = sum;
    }
    __syncthreads();
    if (tid < 16) {
        float mx = -1e30f;
        #pragma unroll
        for (int kk = 0; kk < 16; kk++) mx = fmaxf(mx, P[tid][kk]);
        float sm = 0.f;
        #pragma unroll
        for (int kk = 0; kk < 16; kk++) {
            float p = __expf(P[tid][kk] - mx);
            P[tid][kk] = p; sm += p;
        }
        float inv = 1.f / sm;
        #pragma unroll
        for (int kk = 0; kk < 16; kk++) P[tid][kk] *= inv;
    }
    __syncthreads();
    for (int i = tid; i < 1024; i += 128) {
        int q = i >> 6, d = i & 63;
        float o = 0.f;
        #pragma unroll
        for (int t = 0; t < 16; t++) o += P[q][t] * V[t][d];
        size_t oi = ((size_t)s * Tt + q) * Dd + h * HDm + d;
        __nv_bfloat16 hh, ll; split_bf(o, hh, ll);
        outh[oi] = hh; outl[oi] = ll;
    }
}

// ---------------- Spatial attention: flash-style, S=197, head dim 64 ---------
__global__ __launch_bounds__(128) void spatial_attn(
    const float* __restrict__ qkv,
    __nv_bfloat16* __restrict__ outh, __nv_bfloat16* __restrict__ outl)
{
    const int bh = blockIdx.x;
    const int bt = bh / NHh, h = bh % NHh;
    const int q0 = blockIdx.y * 32;
    const int tid = threadIdx.x;
    constexpr int LD = 72;
    __shared__ float Qs[32][LD], Ks[32][LD], Vs[32][LD], Ps[32][36];

    const float* base = qkv + (size_t)bt * SSP * (3 * Dd) + h * HDm;
    for (int i = tid; i < 2048; i += 128) {
        int r = i >> 6, d = i & 63;
        float v = 0.f;
        if (q0 + r < SSP) v = base[(size_t)(q0 + r) * (3 * Dd) + d] * 0.125f;
        Qs[r][d] = v;
    }
    const int qrow  = tid >> 2;
    const int cbase = (tid & 3) * 8;
    const int dseg  = (tid & 3) * 16;
    float m_i = -1e30f, l_i = 0.f;
    float acc[16];
    #pragma unroll
    for (int u = 0; u < 16; u++) acc[u] = 0.f;

    for (int k0 = 0; k0 < SSP; k0 += 32) {
        __syncthreads();
        for (int i = tid; i < 2048; i += 128) {
            int r = i >> 6, d = i & 63;
            float kv = 0.f, vv = 0.f;
            if (k0 + r < SSP) {
                const float* p = base + (size_t)(k0 + r) * (3 * Dd) + d;
                kv = p[Dd]; vv = p[2 * Dd];
            }
            Ks[r][d] = kv; Vs[r][d] = vv;
        }
        __syncthreads();
        float sreg[8];
        #pragma unroll
        for (int j = 0; j < 8; j++) sreg[j] = 0.f;
        #pragma unroll
        for (int d4 = 0; d4 < 64; d4 += 4) {
            float4 q4 = *reinterpret_cast<const float4*>(&Qs[qrow][d4]);
            #pragma unroll
            for (int j = 0; j < 8; j++) {
                float4 k4 = *reinterpret_cast<const float4*>(&Ks[cbase + j][d4]);
                sreg[j] += q4.x * k4.x + q4.y * k4.y + q4.z * k4.z + q4.w * k4.w;
            }
        }
        float mloc = -1e30f;
        #pragma unroll
        for (int j = 0; j < 8; j++) {
            if (k0 + cbase + j >= SSP) sreg[j] = -1e30f;
            mloc = fmaxf(mloc, sreg[j]);
        }
        mloc = fmaxf(mloc, __shfl_xor_sync(0xffffffffu, mloc, 1));
        mloc = fmaxf(mloc, __shfl_xor_sync(0xffffffffu, mloc, 2));
        float m_new = fmaxf(m_i, mloc);
        float alpha = __expf(m_i - m_new);
        float psum = 0.f;
        #pragma unroll
        for (int j = 0; j < 8; j++) {
            float p = __expf(sreg[j] - m_new);
            Ps[qrow][cbase + j] = p;
            psum += p;
        }
        psum += __shfl_xor_sync(0xffffffffu, psum, 1);
        psum += __shfl_xor_sync(0xffffffffu, psum, 2);
        l_i = l_i * alpha + psum;
        m_i = m_new;
        #pragma unroll
        for (int u = 0; u < 16; u++) acc[u] *= alpha;
        __syncwarp();
        #pragma unroll 4
        for (int kv = 0; kv < 32; kv++) {
            float p = Ps[qrow][kv];
            float4 v0 = *reinterpret_cast<const float4*>(&Vs[kv][dseg]);
            float4 v1 = *reinterpret_cast<const float4*>(&Vs[kv][dseg + 4]);
            float4 v2 = *reinterpret_cast<const float4*>(&Vs[kv][dseg + 8]);
            float4 v3 = *reinterpret_cast<const float4*>(&Vs[kv][dseg + 12]);
            acc[0]  += p * v0.x; acc[1]  += p * v0.y; acc[2]  += p * v0.z; acc[3]  += p * v0.w;
            acc[4]  += p * v1.x; acc[5]  += p * v1.y; acc[6]  += p * v1.z; acc[7]  += p * v1.w;
            acc[8]  += p * v2.x; acc[9]  += p * v2.y; acc[10] += p * v2.z; acc[11] += p * v2.w;
            acc[12] += p * v3.x; acc[13] += p * v3.y; acc[14] += p * v3.z; acc[15] += p * v3.w;
        }
    }
    if (q0 + qrow < SSP) {
        float inv = 1.f / l_i;
        size_t ob = (size_t)(bt * SSP + q0 + qrow) * Dd + h * HDm + dseg;
        #pragma unroll
        for (int u = 0; u < 16; u += 2) {
            __nv_bfloat16 h0, l0, h1, l1;
            split_bf(acc[u] * inv, h0, l0);
            split_bf(acc[u + 1] * inv, h1, l1);
            __nv_bfloat162 ph; ph.x = h0; ph.y = h1;
            __nv_bfloat162 pl; pl.x = l0; pl.y = l1;
            *(__nv_bfloat162*)(outh + ob + u) = ph;
            *(__nv_bfloat162*)(outl + ob + u) = pl;
        }
    }
}

// ---------------- launch ------------------------------------------------------
extern "C" void kernel_launch(void* const* d_in, const int* in_sizes, int n_in,
                              void* d_out, int out_size)
{
    (void)in_sizes; (void)n_in; (void)out_size;
    const float* x        = (const float*)d_in[0];
    const float* tn1_w    = (const float*)d_in[1];
    const float* tn1_b    = (const float*)d_in[2];
    const float* t_qkv_w  = (const float*)d_in[3];
    const float* t_proj_w = (const float*)d_in[4];
    const float* t_proj_b = (const float*)d_in[5];
    const float* tfc_w    = (const float*)d_in[6];
    const float* tfc_b    = (const float*)d_in[7];
    const float* n1_w     = (const float*)d_in[8];
    const float* n1_b     = (const float*)d_in[9];
    const float* s_qkv_w  = (const float*)d_in[10];
    const float* s_proj_w = (const float*)d_in[11];
    const float* s_proj_b = (const float*)d_in[12];
    const float* n2_w     = (const float*)d_in[13];
    const float* n2_b     = (const float*)d_in[14];
    const float* fc1_w    = (const float*)d_in[15];
    const float* fc1_b    = (const float*)d_in[16];
    const float* fc2_w    = (const float*)d_in[17];
    const float* fc2_b    = (const float*)d_in[18];
    float* out = (float*)d_out;

    float *qkv, *xt2, *rs;
    __nv_bfloat16 *lnh, *lnl, *atth, *attl, *tmph, *tmpl, *hidh, *hidl, *wh, *wl;
    cudaGetSymbolAddress((void**)&qkv,  g_qkv);
    cudaGetSymbolAddress((void**)&xt2,  g_xt2);
    cudaGetSymbolAddress((void**)&rs,   g_rs);
    cudaGetSymbolAddress((void**)&lnh,  g_lnh);
    cudaGetSymbolAddress((void**)&lnl,  g_lnl);
    cudaGetSymbolAddress((void**)&atth, g_atth);
    cudaGetSymbolAddress((void**)&attl, g_attl);
    cudaGetSymbolAddress((void**)&tmph, g_tmph);
    cudaGetSymbolAddress((void**)&tmpl, g_tmpl);
    cudaGetSymbolAddress((void**)&hidh, g_hidh);
    cudaGetSymbolAddress((void**)&hidl, g_hidl);
    cudaGetSymbolAddress((void**)&wh,   g_wh);
    cudaGetSymbolAddress((void**)&wl,   g_wl);

    // pad + header + 3 stages of 64KB
    const size_t SMEMSZ = 1024 + 1024 + 3 * 65536;
    cudaFuncSetAttribute(mma_gemm<0,0,0,0>, cudaFuncAttributeMaxDynamicSharedMemorySize, SMEMSZ);
    cudaFuncSetAttribute(mma_gemm<0,0,0,1>, cudaFuncAttributeMaxDynamicSharedMemorySize, SMEMSZ);
    cudaFuncSetAttribute(mma_gemm<0,2,0,0>, cudaFuncAttributeMaxDynamicSharedMemorySize, SMEMSZ);
    cudaFuncSetAttribute(mma_gemm<1,0,0,1>, cudaFuncAttributeMaxDynamicSharedMemorySize, SMEMSZ);
    cudaFuncSetAttribute(mma_gemm<0,0,1,0>, cudaFuncAttributeMaxDynamicSharedMemorySize, SMEMSZ);

    // 0. all weight splits in ONE launch
    wsplit_all<<<9792, 256>>>(t_qkv_w, t_proj_w, tfc_w, s_qkv_w, s_proj_w,
                              fc1_w, fc2_w, wh, wl);
    // 1. temporal LN
    ln_kernel<<<NTOK_T, 256>>>(1, x, nullptr, tn1_w, tn1_b, lnh, lnl);
    // 2. temporal QKV -> f32
    mma_gemm<0,0,0,0><<<dim3(196, 9), 256, SMEMSZ>>>(NTOK_T, 2304, 768,
        lnh, lnl, wh + OFF_TQKV, wl + OFF_TQKV, nullptr, nullptr, qkv, nullptr, nullptr);
    // 3. temporal attention -> hi/lo
    temporal_attn<<<dim3(SEQT, NHh), 128>>>(qkv, atth, attl);
    // 4. temporal proj (+bias) -> hi/lo
    mma_gemm<0,0,0,1><<<dim3(196, 3), 256, SMEMSZ>>>(NTOK_T, 768, 768,
        atth, attl, wh + OFF_TPROJ, wl + OFF_TPROJ, t_proj_b, nullptr, nullptr, tmph, tmpl);
    // 5. tfc (+bias) + residual x (cls-skip) -> xt2 f32
    mma_gemm<0,2,0,0><<<dim3(196, 3), 256, SMEMSZ>>>(NTOK_T, 768, 768,
        tmph, tmpl, wh + OFF_TFC, wl + OFF_TFC, tfc_b, x, xt2, nullptr, nullptr);
    // 6. spatial LN (gather)
    ln_kernel<<<NTOK_S, 256>>>(2, x, xt2, n1_w, n1_b, lnh, lnl);
    // 7. spatial QKV -> f32
    mma_gemm<0,0,0,0><<<dim3(198, 9), 256, SMEMSZ>>>(NTOK_S, 2304, 768,
        lnh, lnl, wh + OFF_SQKV, wl + OFF_SQKV, nullptr, nullptr, qkv, nullptr, nullptr);
    // 8. spatial attention -> hi/lo
    spatial_attn<<<dim3(BT * NHh, 7), 128>>>(qkv, atth, attl);
    // 9. spatial proj (+bias) -> rs f32
    mma_gemm<0,0,0,0><<<dim3(198, 3), 256, SMEMSZ>>>(NTOK_S, 768, 768,
        atth, attl, wh + OFF_SPROJ, wl + OFF_SPROJ, s_proj_b, nullptr, rs, nullptr, nullptr);
    // 10. fused assemble x_new -> d_out + final LN -> hi/lo
    assemble_ln<<<NROWS, 256>>>(x, xt2, rs, n2_w, n2_b, out, lnh, lnl);
    // 11. fc1 (+bias, gelu) -> hi/lo
    mma_gemm<1,0,0,1><<<dim3(198, 12), 256, SMEMSZ>>>(NROWS, 3072, 768,
        lnh, lnl, wh + OFF_FC1, wl + OFF_FC1, fc1_b, nullptr, nullptr, hidh, hidl);
    // 12. fc2 (+bias), accumulate into d_out
    mma_gemm<0,0,1,0><<<dim3(198, 3), 256, SMEMSZ>>>(NROWS, 768, 3072,
        hidh, hidl, wh + OFF_FC2, wl + OFF_FC2, fc2_b, nullptr, out, nullptr, nullptr);
}